// round 12
// baseline (speedup 1.0000x reference)
#include <cuda_runtime.h>
#include <cuda_fp16.h>
#include <mma.h>
#include <math.h>

using namespace nvcuda;

#define NN 50000
#define NE 800000
#define IND 128
#define OUTD 64
#define THALF 64
#define TABN 4096

#define S12_BLOCKS 6250          // NN/8
#define CNT_BLOCKS 391           // ceil(NE/8/256)

// sqrt(1/128)
#define TSCALE 0.08838834764831845f

// ---------------- scratch (static __device__, no allocations) ----------------
__device__ float  g_p1[IND];
__device__ float  g_p2[IND];
__device__ float  g_q[2 * THALF];
__device__ float  g_tab[TABN + 1];
__device__ float  g_s1[NN];
__device__ float  g_s2[NN];
__device__ __align__(32) __half g_hv[NN * OUTD];      // fp16 value rows
__device__ float2 g_pair[NE];                 // (w=exp(leaky(e)), bitcast(src))
__device__ int    g_cnt[NN];                  // zero-init at load; self-restoring
__device__ int    g_off[NN + 1];
__device__ int    g_cur[NN];

// ---------------- setup: p1/p2, q, temporal table (19 blocks) ----------------
__global__ void k_setup(const float* __restrict__ W, const float* __restrict__ Wt,
                        const float* __restrict__ a, const float* __restrict__ omega) {
    int b = blockIdx.x;
    int t = threadIdx.x;

    if (b == 0) {
        if (t < 128) {
            float s = 0.f;
            #pragma unroll 8
            for (int i = 0; i < 64; i++) s += W[i * 128 + t] * a[i];
            g_p1[t] = s;
        } else {
            int k = t - 128;
            float s = 0.f;
            #pragma unroll 8
            for (int i = 0; i < 64; i++) s += W[i * 128 + k] * a[64 + i];
            g_p2[k] = s;
        }
    } else if (b == 1) {
        if (t < 128) {
            float s = 0.f;
            #pragma unroll 8
            for (int i = 0; i < 64; i++) s += Wt[i * 128 + t] * a[128 + i];
            g_q[t] = s;
        }
    } else {
        __shared__ float qs[128];
        if (t < 128) {
            float s = 0.f;
            #pragma unroll 8
            for (int i = 0; i < 64; i++) s += Wt[i * 128 + t] * a[128 + i];
            qs[t] = s;
        }
        __syncthreads();
        int idx = (b - 2) * 256 + t;      // blocks 2..18 cover 0..4352 > TABN
        if (idx <= TABN) {
            float tt = (float)idx / (float)TABN;
            float s = 0.f;
            #pragma unroll 4
            for (int j = 0; j < THALF; j++) {
                float sn, cs;
                __sincosf(tt * omega[j], &sn, &cs);
                s += sn * qs[2 * j] + cs * qs[2 * j + 1];
            }
            g_tab[idx] = s * TSCALE;
        }
    }
}

// ---------------- fused s12 + degree histogram (heterogeneous blocks) --------
__global__ void k_sc(const float* __restrict__ x, const int* __restrict__ dst) {
    int b = blockIdx.x;
    int tid = threadIdx.x;

    if (b < S12_BLOCKS) {
        // s12 role: warp per node
        int n = b * 8 + (tid >> 5);
        int lane = tid & 31;
        if (n >= NN) return;
        float4 v  = ((const float4*)(x + (size_t)n * IND))[lane];
        float4 p1 = ((const float4*)g_p1)[lane];
        float4 p2 = ((const float4*)g_p2)[lane];
        float d1 = v.x * p1.x + v.y * p1.y + v.z * p1.z + v.w * p1.w;
        float d2 = v.x * p2.x + v.y * p2.y + v.z * p2.z + v.w * p2.w;
        #pragma unroll
        for (int o = 16; o; o >>= 1) {
            d1 += __shfl_xor_sync(0xffffffffu, d1, o);
            d2 += __shfl_xor_sync(0xffffffffu, d2, o);
        }
        if (lane == 0) { g_s1[n] = d1; g_s2[n] = d2; }
    } else {
        // count role: 8 edges per thread
        int i = (b - S12_BLOCKS) * 256 + tid;
        if (i * 8 >= NE) return;
        int4 a4 = ((const int4*)dst)[i * 2];
        int4 b4 = ((const int4*)dst)[i * 2 + 1];
        atomicAdd(&g_cnt[a4.x], 1);
        atomicAdd(&g_cnt[a4.y], 1);
        atomicAdd(&g_cnt[a4.z], 1);
        atomicAdd(&g_cnt[a4.w], 1);
        atomicAdd(&g_cnt[b4.x], 1);
        atomicAdd(&g_cnt[b4.y], 1);
        atomicAdd(&g_cnt[b4.z], 1);
        atomicAdd(&g_cnt[b4.w], 1);
    }
}

// ---------------- hv = X @ Wv^T via wmma, fully self-contained ---------------
// Each block converts Wv fp32->fp16 into smem (L2-resident source), so this
// kernel has NO producer dependencies and launches at t=0 on its own stream.
__global__ void __launch_bounds__(256) k_hv(const float* __restrict__ x,
                                            const float* __restrict__ Wv) {
    __shared__ __align__(32) half sX[64 * 136];    // 17408 B
    __shared__ __align__(32) half sB[64 * 136];    // 17408 B
    float* stage = (float*)sX;                     // aliased, sync-guarded

    int n0 = blockIdx.x * 64;
    int tid = threadIdx.x;
    int wid = tid >> 5;
    int rg = wid >> 1;          // row group 0..3
    int cg = wid & 1;           // col group 0..1

    // load + convert B: Wv[n][k] fp32 -> sB[n*136+k] fp16
    for (int i = tid; i < 2048; i += 256) {        // 2048 float4 = 8192 floats
        int n  = i >> 5;                           // 32 float4 per row
        int c4 = i & 31;
        float4 v = *(const float4*)(Wv + n * 128 + c4 * 4);
        *(__half2*)&sB[n * 136 + c4 * 4]     = __floats2half2_rn(v.x, v.y);
        *(__half2*)&sB[n * 136 + c4 * 4 + 2] = __floats2half2_rn(v.z, v.w);
    }

    // load X tile fp32 -> fp16 (coalesced float4 reads)
    for (int i = tid; i < 64 * 32; i += 256) {
        int r  = i >> 5;
        int c4 = i & 31;
        int n = n0 + r;
        float4 v = (n < NN)
            ? *(const float4*)(x + (size_t)n * 128 + c4 * 4)
            : make_float4(0.f, 0.f, 0.f, 0.f);
        *(__half2*)&sX[r * 136 + c4 * 4]     = __floats2half2_rn(v.x, v.y);
        *(__half2*)&sX[r * 136 + c4 * 4 + 2] = __floats2half2_rn(v.z, v.w);
    }
    __syncthreads();

    wmma::fragment<wmma::matrix_a, 16, 16, 16, half, wmma::row_major> af;
    wmma::fragment<wmma::matrix_b, 16, 16, 16, half, wmma::col_major> bf;
    wmma::fragment<wmma::accumulator, 16, 16, 16, float> acc[2];
    #pragma unroll
    for (int j = 0; j < 2; j++) wmma::fill_fragment(acc[j], 0.f);

    #pragma unroll
    for (int ks = 0; ks < 8; ks++) {
        wmma::load_matrix_sync(af, sX + rg * 16 * 136 + ks * 16, 136);
        #pragma unroll
        for (int j = 0; j < 2; j++) {
            wmma::load_matrix_sync(bf, sB + (cg * 32 + j * 16) * 136 + ks * 16, 136);
            wmma::mma_sync(acc[j], af, bf, acc[j]);
        }
    }
    __syncthreads();

    #pragma unroll
    for (int j = 0; j < 2; j++)
        wmma::store_matrix_sync(stage + rg * 16 * 64 + cg * 32 + j * 16, acc[j], 64,
                                wmma::mem_row_major);
    __syncthreads();

    for (int i = tid; i < 64 * 32; i += 256) {
        int r  = i >> 5;
        int c2 = i & 31;
        int n = n0 + r;
        if (n < NN) {
            __half2 h = __floats2half2_rn(stage[r * 64 + c2 * 2],
                                          stage[r * 64 + c2 * 2 + 1]);
            *(__half2*)&g_hv[(size_t)n * 64 + c2 * 2] = h;
        }
    }
}

// ---------------- single-kernel scan: g_cnt -> g_off/g_cur, self-zeroing -----
__global__ void __launch_bounds__(1024) k_scanall() {
    const int C = 52;
    __shared__ int warpsum[32];
    int tid = threadIdx.x;
    int lane = tid & 31;
    int wid  = tid >> 5;
    int base = tid * C;

    int s = 0;
    #pragma unroll
    for (int j = 0; j < C; j += 4) {
        int idx = base + j;
        if (idx < NN) {
            int4 v = *(const int4*)&g_cnt[idx];
            s += (v.x + v.y) + (v.z + v.w);
        }
    }

    int x = s;
    #pragma unroll
    for (int o = 1; o < 32; o <<= 1) {
        int y = __shfl_up_sync(0xffffffffu, x, o);
        if (lane >= o) x += y;
    }
    if (lane == 31) warpsum[wid] = x;
    __syncthreads();
    if (wid == 0) {
        int w = warpsum[lane];
        int xw = w;
        #pragma unroll
        for (int o = 1; o < 32; o <<= 1) {
            int y = __shfl_up_sync(0xffffffffu, xw, o);
            if (lane >= o) xw += y;
        }
        warpsum[lane] = xw - w;
    }
    __syncthreads();
    int run = (x - s) + warpsum[wid];

    const int4 zero4 = make_int4(0, 0, 0, 0);
    #pragma unroll
    for (int j = 0; j < C; j += 4) {
        int idx = base + j;
        if (idx < NN) {
            int4 v = *(const int4*)&g_cnt[idx];
            int o0 = run;
            int o1 = o0 + v.x;
            int o2 = o1 + v.y;
            int o3 = o2 + v.z;
            run = o3 + v.w;
            int4 ov = make_int4(o0, o1, o2, o3);
            *(int4*)&g_off[idx] = ov;
            *(int4*)&g_cur[idx] = ov;
            *(int4*)&g_cnt[idx] = zero4;   // restore invariant for next replay
        }
    }
    if (tid == 0) g_off[NN] = NE;
}

// ---------------- fused logit + exp + scatter into CSR (4 edges/thread) ------
__global__ void k_scatter(const float* __restrict__ td, const int* __restrict__ src,
                          const int* __restrict__ dst, const float* __restrict__ omega) {
    int i = blockIdx.x * 256 + threadIdx.x;
    if (i * 4 >= NE) return;
    float4 t4 = ((const float4*)td)[i];
    int4   s4 = ((const int4*)src)[i];
    int4   d4 = ((const int4*)dst)[i];

    float tv[4] = {t4.x, t4.y, t4.z, t4.w};
    int   sv[4] = {s4.x, s4.y, s4.z, s4.w};
    int   dv[4] = {d4.x, d4.y, d4.z, d4.w};

    #pragma unroll
    for (int j = 0; j < 4; j++) {
        float t = tv[j];
        int s = sv[j], d = dv[j];
        float tt;
        if (t >= 0.f && t <= 1.f) {
            float u = t * (float)TABN;
            int i0 = (int)u;
            if (i0 >= TABN) i0 = TABN - 1;
            float f = u - (float)i0;
            float v0 = g_tab[i0], v1 = g_tab[i0 + 1];
            tt = v0 + f * (v1 - v0);
        } else {
            float acc = 0.f;
            for (int jj = 0; jj < THALF; jj++) {
                float sn, cs;
                sincosf(t * omega[jj], &sn, &cs);
                acc += sn * g_q[2 * jj] + cs * g_q[2 * jj + 1];
            }
            tt = acc * TSCALE;
        }
        float e = g_s1[s] + g_s2[d] + tt;
        e = (e > 0.f) ? e : 0.2f * e;       // LeakyReLU(0.2)
        float w = __expf(e);                // softmax numerator (logits are O(1))
        int pos = atomicAdd(&g_cur[d], 1);
        g_pair[pos] = make_float2(w, __int_as_float(s));
    }
}

// ---------------- warp-per-node single-pass softmax-aggregate ----------------
__global__ void k_agg(float* __restrict__ out) {
    int n = blockIdx.x * 8 + (threadIdx.x >> 5);
    int lane = threadIdx.x & 31;
    if (n >= NN) return;
    int start = g_off[n], end = g_off[n + 1];

    float wsum = 0.f, ax = 0.f, ay = 0.f;
    int k = start;
    for (; k + 4 <= end; k += 4) {
        float2 p0 = g_pair[k],     p1 = g_pair[k + 1];
        float2 p2 = g_pair[k + 2], p3 = g_pair[k + 3];
        int j0 = __float_as_int(p0.y), j1 = __float_as_int(p1.y);
        int j2 = __float_as_int(p2.y), j3 = __float_as_int(p3.y);
        __half2 h0 = ((const __half2*)(g_hv + (size_t)j0 * 64))[lane];
        __half2 h1 = ((const __half2*)(g_hv + (size_t)j1 * 64))[lane];
        __half2 h2 = ((const __half2*)(g_hv + (size_t)j2 * 64))[lane];
        __half2 h3 = ((const __half2*)(g_hv + (size_t)j3 * 64))[lane];
        float2 v0 = __half22float2(h0), v1 = __half22float2(h1);
        float2 v2 = __half22float2(h2), v3 = __half22float2(h3);
        wsum += (p0.x + p1.x) + (p2.x + p3.x);
        ax = fmaf(p0.x, v0.x, ax); ay = fmaf(p0.x, v0.y, ay);
        ax = fmaf(p1.x, v1.x, ax); ay = fmaf(p1.x, v1.y, ay);
        ax = fmaf(p2.x, v2.x, ax); ay = fmaf(p2.x, v2.y, ay);
        ax = fmaf(p3.x, v3.x, ax); ay = fmaf(p3.x, v3.y, ay);
    }
    for (; k < end; k++) {
        float2 p = g_pair[k];
        float2 v = __half22float2(
            ((const __half2*)(g_hv + (size_t)__float_as_int(p.y) * 64))[lane]);
        wsum += p.x;
        ax = fmaf(p.x, v.x, ax);
        ay = fmaf(p.x, v.y, ay);
    }
    float inv = (end > start) ? 1.f / wsum : 0.f;
    ((float2*)(out + (size_t)n * 64))[lane] = make_float2(ax * inv, ay * inv);
}

// ---------------- launcher: hv at t=0 on side stream; short main chain -------
extern "C" void kernel_launch(void* const* d_in, const int* in_sizes, int n_in,
                              void* d_out, int out_size) {
    const float* node_feats = (const float*)d_in[0];
    const float* time_diff  = (const float*)d_in[1];
    const int*   src        = (const int*)d_in[2];
    const int*   dst        = (const int*)d_in[3];
    const float* W          = (const float*)d_in[4];
    const float* Wv         = (const float*)d_in[5];
    const float* omega      = (const float*)d_in[6];
    const float* Wt         = (const float*)d_in[7];
    const float* a          = (const float*)d_in[8];
    float* out = (float*)d_out;

    static cudaStream_t sC = nullptr;
    static cudaEvent_t evFork = nullptr, evHv = nullptr;
    if (!sC) {
        cudaStreamCreateWithFlags(&sC, cudaStreamNonBlocking);
        cudaEventCreateWithFlags(&evFork, cudaEventDisableTiming);
        cudaEventCreateWithFlags(&evHv,   cudaEventDisableTiming);
    }

    // branch C: value projection, zero dependencies, starts immediately
    cudaEventRecord(evFork, 0);
    cudaStreamWaitEvent(sC, evFork, 0);
    k_hv<<<(NN + 63) / 64, 256, 0, sC>>>(node_feats, Wv);
    cudaEventRecord(evHv, sC);

    // main chain
    k_setup<<<19, 256>>>(W, Wt, a, omega);
    k_sc<<<S12_BLOCKS + CNT_BLOCKS, 256>>>(node_feats, dst);
    k_scanall<<<1, 1024>>>();
    k_scatter<<<(NE / 4 + 255) / 256, 256>>>(time_diff, src, dst, omega);
    cudaStreamWaitEvent(0, evHv, 0);
    k_agg<<<(NN + 7) / 8, 256>>>(out);
}

// round 13
// speedup vs baseline: 1.3741x; 1.3741x over previous
#include <cuda_runtime.h>
#include <cuda_fp16.h>
#include <mma.h>
#include <math.h>

using namespace nvcuda;

#define NN 50000
#define NE 800000
#define IND 128
#define OUTD 64
#define THALF 64
#define TABN 4096
#define SCAN_BLOCKS 49           // ceil(50000 / 1024)

#define S12_BLOCKS 6250          // NN/8
#define CNT_BLOCKS 391           // ceil(NE/8/256)

// sqrt(1/128)
#define TSCALE 0.08838834764831845f

// ---------------- scratch (static __device__, no allocations) ----------------
__device__ float  g_p1[IND];
__device__ float  g_p2[IND];
__device__ float  g_q[2 * THALF];
__device__ float  g_tab[TABN + 1];
__device__ float  g_s1[NN];
__device__ float  g_s2[NN];
__device__ __align__(32) __half g_hv[NN * OUTD];      // fp16 value rows
__device__ float2 g_pair[NE];                 // (w=exp(leaky(e)), bitcast(src))
__device__ int    g_cnt[NN];                  // zero-init at load; self-restoring
__device__ int    g_off[NN + 1];
__device__ int    g_cur[NN];
__device__ int    g_bsum[SCAN_BLOCKS];

// ---------------- setup: p1/p2, q, temporal table (19 blocks) ----------------
__global__ void k_setup(const float* __restrict__ W, const float* __restrict__ Wt,
                        const float* __restrict__ a, const float* __restrict__ omega) {
    int b = blockIdx.x;
    int t = threadIdx.x;

    if (b == 0) {
        if (t < 128) {
            float s = 0.f;
            #pragma unroll 8
            for (int i = 0; i < 64; i++) s += W[i * 128 + t] * a[i];
            g_p1[t] = s;
        } else {
            int k = t - 128;
            float s = 0.f;
            #pragma unroll 8
            for (int i = 0; i < 64; i++) s += W[i * 128 + k] * a[64 + i];
            g_p2[k] = s;
        }
    } else if (b == 1) {
        if (t < 128) {
            float s = 0.f;
            #pragma unroll 8
            for (int i = 0; i < 64; i++) s += Wt[i * 128 + t] * a[128 + i];
            g_q[t] = s;
        }
    } else {
        __shared__ float qs[128];
        if (t < 128) {
            float s = 0.f;
            #pragma unroll 8
            for (int i = 0; i < 64; i++) s += Wt[i * 128 + t] * a[128 + i];
            qs[t] = s;
        }
        __syncthreads();
        int idx = (b - 2) * 256 + t;      // blocks 2..18 cover table
        if (idx <= TABN) {
            float tt = (float)idx / (float)TABN;
            float s = 0.f;
            #pragma unroll 4
            for (int j = 0; j < THALF; j++) {
                float sn, cs;
                __sincosf(tt * omega[j], &sn, &cs);
                s += sn * qs[2 * j] + cs * qs[2 * j + 1];
            }
            g_tab[idx] = s * TSCALE;
        }
    }
}

// ---------------- fused s12 + degree histogram (heterogeneous blocks) --------
__global__ void k_sc(const float* __restrict__ x, const int* __restrict__ dst) {
    int b = blockIdx.x;
    int tid = threadIdx.x;

    if (b < S12_BLOCKS) {
        // s12 role: warp per node
        int n = b * 8 + (tid >> 5);
        int lane = tid & 31;
        if (n >= NN) return;
        float4 v  = ((const float4*)(x + (size_t)n * IND))[lane];
        float4 p1 = ((const float4*)g_p1)[lane];
        float4 p2 = ((const float4*)g_p2)[lane];
        float d1 = v.x * p1.x + v.y * p1.y + v.z * p1.z + v.w * p1.w;
        float d2 = v.x * p2.x + v.y * p2.y + v.z * p2.z + v.w * p2.w;
        #pragma unroll
        for (int o = 16; o; o >>= 1) {
            d1 += __shfl_xor_sync(0xffffffffu, d1, o);
            d2 += __shfl_xor_sync(0xffffffffu, d2, o);
        }
        if (lane == 0) { g_s1[n] = d1; g_s2[n] = d2; }
    } else {
        // count role: 8 edges per thread
        int i = (b - S12_BLOCKS) * 256 + tid;
        if (i * 8 >= NE) return;
        int4 a4 = ((const int4*)dst)[i * 2];
        int4 b4 = ((const int4*)dst)[i * 2 + 1];
        atomicAdd(&g_cnt[a4.x], 1);
        atomicAdd(&g_cnt[a4.y], 1);
        atomicAdd(&g_cnt[a4.z], 1);
        atomicAdd(&g_cnt[a4.w], 1);
        atomicAdd(&g_cnt[b4.x], 1);
        atomicAdd(&g_cnt[b4.y], 1);
        atomicAdd(&g_cnt[b4.z], 1);
        atomicAdd(&g_cnt[b4.w], 1);
    }
}

// ---------------- hv = X @ Wv^T via wmma, fully self-contained ---------------
__global__ void __launch_bounds__(256) k_hv(const float* __restrict__ x,
                                            const float* __restrict__ Wv) {
    __shared__ __align__(32) half sX[64 * 136];    // 17408 B
    __shared__ __align__(32) half sB[64 * 136];    // 17408 B
    float* stage = (float*)sX;                     // aliased, sync-guarded

    int n0 = blockIdx.x * 64;
    int tid = threadIdx.x;
    int wid = tid >> 5;
    int rg = wid >> 1;          // row group 0..3
    int cg = wid & 1;           // col group 0..1

    // load + convert B: Wv[n][k] fp32 -> sB[n*136+k] fp16 (L2-resident source)
    for (int i = tid; i < 2048; i += 256) {
        int n  = i >> 5;
        int c4 = i & 31;
        float4 v = *(const float4*)(Wv + n * 128 + c4 * 4);
        *(__half2*)&sB[n * 136 + c4 * 4]     = __floats2half2_rn(v.x, v.y);
        *(__half2*)&sB[n * 136 + c4 * 4 + 2] = __floats2half2_rn(v.z, v.w);
    }

    // load X tile fp32 -> fp16
    for (int i = tid; i < 64 * 32; i += 256) {
        int r  = i >> 5;
        int c4 = i & 31;
        int n = n0 + r;
        float4 v = (n < NN)
            ? *(const float4*)(x + (size_t)n * 128 + c4 * 4)
            : make_float4(0.f, 0.f, 0.f, 0.f);
        *(__half2*)&sX[r * 136 + c4 * 4]     = __floats2half2_rn(v.x, v.y);
        *(__half2*)&sX[r * 136 + c4 * 4 + 2] = __floats2half2_rn(v.z, v.w);
    }
    __syncthreads();

    wmma::fragment<wmma::matrix_a, 16, 16, 16, half, wmma::row_major> af;
    wmma::fragment<wmma::matrix_b, 16, 16, 16, half, wmma::col_major> bf;
    wmma::fragment<wmma::accumulator, 16, 16, 16, float> acc[2];
    #pragma unroll
    for (int j = 0; j < 2; j++) wmma::fill_fragment(acc[j], 0.f);

    #pragma unroll
    for (int ks = 0; ks < 8; ks++) {
        wmma::load_matrix_sync(af, sX + rg * 16 * 136 + ks * 16, 136);
        #pragma unroll
        for (int j = 0; j < 2; j++) {
            wmma::load_matrix_sync(bf, sB + (cg * 32 + j * 16) * 136 + ks * 16, 136);
            wmma::mma_sync(acc[j], af, bf, acc[j]);
        }
    }
    __syncthreads();

    #pragma unroll
    for (int j = 0; j < 2; j++)
        wmma::store_matrix_sync(stage + rg * 16 * 64 + cg * 32 + j * 16, acc[j], 64,
                                wmma::mem_row_major);
    __syncthreads();

    for (int i = tid; i < 64 * 32; i += 256) {
        int r  = i >> 5;
        int c2 = i & 31;
        int n = n0 + r;
        if (n < NN) {
            __half2 h = __floats2half2_rn(stage[r * 64 + c2 * 2],
                                          stage[r * 64 + c2 * 2 + 1]);
            *(__half2*)&g_hv[(size_t)n * 64 + c2 * 2] = h;
        }
    }
}

// ---------------- scan phase 1: per-block exclusive scan (49 blocks) ---------
__global__ void __launch_bounds__(1024) k_scan1() {
    __shared__ int warpsum[32];
    int tid = threadIdx.x;
    int gid = blockIdx.x * 1024 + tid;
    int lane = tid & 31;
    int wid  = tid >> 5;

    int v = (gid < NN) ? g_cnt[gid] : 0;

    int x = v;
    #pragma unroll
    for (int o = 1; o < 32; o <<= 1) {
        int y = __shfl_up_sync(0xffffffffu, x, o);
        if (lane >= o) x += y;
    }
    if (lane == 31) warpsum[wid] = x;
    __syncthreads();

    if (wid == 0) {
        int w = warpsum[lane];
        int xw = w;
        #pragma unroll
        for (int o = 1; o < 32; o <<= 1) {
            int y = __shfl_up_sync(0xffffffffu, xw, o);
            if (lane >= o) xw += y;
        }
        warpsum[lane] = xw - w;
        if (lane == 31) g_bsum[blockIdx.x] = xw;
    }
    __syncthreads();

    int excl = x - v + warpsum[wid];
    if (gid < NN) g_off[gid] = excl;
}

// ---------------- scan phase 2+3: add block prefix, fill g_cur, zero g_cnt ---
__global__ void __launch_bounds__(1024) k_scan23() {
    __shared__ int spre;
    int b = blockIdx.x;
    if (threadIdx.x < 32) {
        int lane = threadIdx.x;
        int acc = 0;
        for (int j = lane; j < b; j += 32) acc += g_bsum[j];
        #pragma unroll
        for (int o = 16; o; o >>= 1) acc += __shfl_xor_sync(0xffffffffu, acc, o);
        if (lane == 0) spre = acc;
    }
    __syncthreads();
    int gid = b * 1024 + threadIdx.x;
    if (gid < NN) {
        int o = g_off[gid] + spre;
        g_off[gid] = o;
        g_cur[gid] = o;
        g_cnt[gid] = 0;               // restore invariant for next replay
    }
    if (b == 0 && threadIdx.x == 0) g_off[NN] = NE;   // counts sum to NE
}

// ---------------- fused logit + exp + scatter into CSR (4 edges/thread) ------
__global__ void k_scatter(const float* __restrict__ td, const int* __restrict__ src,
                          const int* __restrict__ dst, const float* __restrict__ omega) {
    int i = blockIdx.x * 256 + threadIdx.x;
    if (i * 4 >= NE) return;
    float4 t4 = ((const float4*)td)[i];
    int4   s4 = ((const int4*)src)[i];
    int4   d4 = ((const int4*)dst)[i];

    float tv[4] = {t4.x, t4.y, t4.z, t4.w};
    int   sv[4] = {s4.x, s4.y, s4.z, s4.w};
    int   dv[4] = {d4.x, d4.y, d4.z, d4.w};

    #pragma unroll
    for (int j = 0; j < 4; j++) {
        float t = tv[j];
        int s = sv[j], d = dv[j];
        float tt;
        if (t >= 0.f && t <= 1.f) {
            float u = t * (float)TABN;
            int i0 = (int)u;
            if (i0 >= TABN) i0 = TABN - 1;
            float f = u - (float)i0;
            float v0 = g_tab[i0], v1 = g_tab[i0 + 1];
            tt = v0 + f * (v1 - v0);
        } else {
            float acc = 0.f;
            for (int jj = 0; jj < THALF; jj++) {
                float sn, cs;
                sincosf(t * omega[jj], &sn, &cs);
                acc += sn * g_q[2 * jj] + cs * g_q[2 * jj + 1];
            }
            tt = acc * TSCALE;
        }
        float e = g_s1[s] + g_s2[d] + tt;
        e = (e > 0.f) ? e : 0.2f * e;       // LeakyReLU(0.2)
        float w = __expf(e);                // softmax numerator (logits are O(1))
        int pos = atomicAdd(&g_cur[d], 1);
        g_pair[pos] = make_float2(w, __int_as_float(s));
    }
}

// ---------------- warp-per-node single-pass softmax-aggregate ----------------
__global__ void k_agg(float* __restrict__ out) {
    int n = blockIdx.x * 8 + (threadIdx.x >> 5);
    int lane = threadIdx.x & 31;
    if (n >= NN) return;
    int start = g_off[n], end = g_off[n + 1];

    float wsum = 0.f, ax = 0.f, ay = 0.f;
    int k = start;
    for (; k + 4 <= end; k += 4) {
        float2 p0 = g_pair[k],     p1 = g_pair[k + 1];
        float2 p2 = g_pair[k + 2], p3 = g_pair[k + 3];
        int j0 = __float_as_int(p0.y), j1 = __float_as_int(p1.y);
        int j2 = __float_as_int(p2.y), j3 = __float_as_int(p3.y);
        __half2 h0 = ((const __half2*)(g_hv + (size_t)j0 * 64))[lane];
        __half2 h1 = ((const __half2*)(g_hv + (size_t)j1 * 64))[lane];
        __half2 h2 = ((const __half2*)(g_hv + (size_t)j2 * 64))[lane];
        __half2 h3 = ((const __half2*)(g_hv + (size_t)j3 * 64))[lane];
        float2 v0 = __half22float2(h0), v1 = __half22float2(h1);
        float2 v2 = __half22float2(h2), v3 = __half22float2(h3);
        wsum += (p0.x + p1.x) + (p2.x + p3.x);
        ax = fmaf(p0.x, v0.x, ax); ay = fmaf(p0.x, v0.y, ay);
        ax = fmaf(p1.x, v1.x, ax); ay = fmaf(p1.x, v1.y, ay);
        ax = fmaf(p2.x, v2.x, ax); ay = fmaf(p2.x, v2.y, ay);
        ax = fmaf(p3.x, v3.x, ax); ay = fmaf(p3.x, v3.y, ay);
    }
    for (; k < end; k++) {
        float2 p = g_pair[k];
        float2 v = __half22float2(
            ((const __half2*)(g_hv + (size_t)__float_as_int(p.y) * 64))[lane]);
        wsum += p.x;
        ax = fmaf(p.x, v.x, ax);
        ay = fmaf(p.x, v.y, ay);
    }
    float inv = (end > start) ? 1.f / wsum : 0.f;
    ((float2*)(out + (size_t)n * 64))[lane] = make_float2(ax * inv, ay * inv);
}

// ---------------- launcher: hv at t=0 on side stream; short main chain -------
extern "C" void kernel_launch(void* const* d_in, const int* in_sizes, int n_in,
                              void* d_out, int out_size) {
    const float* node_feats = (const float*)d_in[0];
    const float* time_diff  = (const float*)d_in[1];
    const int*   src        = (const int*)d_in[2];
    const int*   dst        = (const int*)d_in[3];
    const float* W          = (const float*)d_in[4];
    const float* Wv         = (const float*)d_in[5];
    const float* omega      = (const float*)d_in[6];
    const float* Wt         = (const float*)d_in[7];
    const float* a          = (const float*)d_in[8];
    float* out = (float*)d_out;

    static cudaStream_t sC = nullptr;
    static cudaEvent_t evFork = nullptr, evHv = nullptr;
    if (!sC) {
        cudaStreamCreateWithFlags(&sC, cudaStreamNonBlocking);
        cudaEventCreateWithFlags(&evFork, cudaEventDisableTiming);
        cudaEventCreateWithFlags(&evHv,   cudaEventDisableTiming);
    }

    // branch C: value projection, zero dependencies, starts immediately
    cudaEventRecord(evFork, 0);
    cudaStreamWaitEvent(sC, evFork, 0);
    k_hv<<<(NN + 63) / 64, 256, 0, sC>>>(node_feats, Wv);
    cudaEventRecord(evHv, sC);

    // main chain
    k_setup<<<19, 256>>>(W, Wt, a, omega);
    k_sc<<<S12_BLOCKS + CNT_BLOCKS, 256>>>(node_feats, dst);
    k_scan1<<<SCAN_BLOCKS, 1024>>>();
    k_scan23<<<SCAN_BLOCKS, 1024>>>();
    k_scatter<<<(NE / 4 + 255) / 256, 256>>>(time_diff, src, dst, omega);
    cudaStreamWaitEvent(0, evHv, 0);
    k_agg<<<(NN + 7) / 8, 256>>>(out);
}

// round 14
// speedup vs baseline: 1.5641x; 1.1383x over previous
#include <cuda_runtime.h>
#include <cuda_fp16.h>
#include <mma.h>
#include <math.h>

using namespace nvcuda;

#define NN 50000
#define NE 800000
#define IND 128
#define OUTD 64
#define THALF 64
#define TABN 4096
#define SCAN_BLOCKS 49           // ceil(50000 / 1024)
#define CNT_BLOCKS 391           // ceil(NE/8/256)

// sqrt(1/128)
#define TSCALE 0.08838834764831845f

// ---------------- scratch (static __device__, no allocations) ----------------
__device__ float  g_p1[IND];
__device__ float  g_p2[IND];
__device__ float  g_q[2 * THALF];
__device__ float  g_tab[TABN + 1];
__device__ float  g_s1[NN];
__device__ float  g_s2[NN];
__device__ __align__(32) __half g_hv[NN * OUTD];      // fp16 value rows
__device__ float2 g_pair[NE];                 // (w=exp(leaky(e)), bitcast(src))
__device__ int    g_cnt[NN];                  // zero-init at load; self-restoring
__device__ int    g_off[NN + 1];
__device__ int    g_cur[NN];
__device__ int    g_bsum[SCAN_BLOCKS];

// ---------------- setup: p1/p2, q, temporal table (19 blocks) ----------------
__global__ void k_setup(const float* __restrict__ W, const float* __restrict__ Wt,
                        const float* __restrict__ a, const float* __restrict__ omega) {
    int b = blockIdx.x;
    int t = threadIdx.x;

    if (b == 0) {
        if (t < 128) {
            float s = 0.f;
            #pragma unroll 8
            for (int i = 0; i < 64; i++) s += W[i * 128 + t] * a[i];
            g_p1[t] = s;
        } else {
            int k = t - 128;
            float s = 0.f;
            #pragma unroll 8
            for (int i = 0; i < 64; i++) s += W[i * 128 + k] * a[64 + i];
            g_p2[k] = s;
        }
    } else if (b == 1) {
        if (t < 128) {
            float s = 0.f;
            #pragma unroll 8
            for (int i = 0; i < 64; i++) s += Wt[i * 128 + t] * a[128 + i];
            g_q[t] = s;
        }
    } else {
        __shared__ float qs[128];
        if (t < 128) {
            float s = 0.f;
            #pragma unroll 8
            for (int i = 0; i < 64; i++) s += Wt[i * 128 + t] * a[128 + i];
            qs[t] = s;
        }
        __syncthreads();
        int idx = (b - 2) * 256 + t;      // blocks 2..18 cover table
        if (idx <= TABN) {
            float tt = (float)idx / (float)TABN;
            float s = 0.f;
            #pragma unroll 4
            for (int j = 0; j < THALF; j++) {
                float sn, cs;
                __sincosf(tt * omega[j], &sn, &cs);
                s += sn * qs[2 * j] + cs * qs[2 * j + 1];
            }
            g_tab[idx] = s * TSCALE;
        }
    }
}

// ---------------- degree histogram (8 edges per thread, 2x int4 load) --------
__global__ void k_count(const int* __restrict__ dst) {
    int i = blockIdx.x * 256 + threadIdx.x;      // NE/8 = 100000 threads
    if (i * 8 >= NE) return;
    int4 a4 = ((const int4*)dst)[i * 2];
    int4 b4 = ((const int4*)dst)[i * 2 + 1];
    atomicAdd(&g_cnt[a4.x], 1);
    atomicAdd(&g_cnt[a4.y], 1);
    atomicAdd(&g_cnt[a4.z], 1);
    atomicAdd(&g_cnt[a4.w], 1);
    atomicAdd(&g_cnt[b4.x], 1);
    atomicAdd(&g_cnt[b4.y], 1);
    atomicAdd(&g_cnt[b4.z], 1);
    atomicAdd(&g_cnt[b4.w], 1);
}

// ---------------- hv = X @ Wv^T via wmma + fused s1/s2 -----------------------
// Depends only on setup (p1/p2). X read ONCE: fp16 tile feeds both the tensor
// GEMM and the per-node attention scalars.
__global__ void __launch_bounds__(256) k_hv(const float* __restrict__ x,
                                            const float* __restrict__ Wv) {
    __shared__ __align__(32) half sX[64 * 136];    // 17408 B
    __shared__ __align__(32) half sB[64 * 136];    // 17408 B
    float* stage = (float*)sX;                     // aliased, sync-guarded

    int n0 = blockIdx.x * 64;
    int tid = threadIdx.x;
    int wid = tid >> 5;
    int rg = wid >> 1;          // row group 0..3
    int cg = wid & 1;           // col group 0..1

    // load + convert B: Wv[n][k] fp32 -> sB[n*136+k] fp16 (L2-resident source)
    for (int i = tid; i < 2048; i += 256) {
        int n  = i >> 5;
        int c4 = i & 31;
        float4 v = *(const float4*)(Wv + n * 128 + c4 * 4);
        *(__half2*)&sB[n * 136 + c4 * 4]     = __floats2half2_rn(v.x, v.y);
        *(__half2*)&sB[n * 136 + c4 * 4 + 2] = __floats2half2_rn(v.z, v.w);
    }

    // load X tile fp32 -> fp16
    for (int i = tid; i < 64 * 32; i += 256) {
        int r  = i >> 5;
        int c4 = i & 31;
        int n = n0 + r;
        float4 v = (n < NN)
            ? *(const float4*)(x + (size_t)n * 128 + c4 * 4)
            : make_float4(0.f, 0.f, 0.f, 0.f);
        *(__half2*)&sX[r * 136 + c4 * 4]     = __floats2half2_rn(v.x, v.y);
        *(__half2*)&sX[r * 136 + c4 * 4 + 2] = __floats2half2_rn(v.z, v.w);
    }
    __syncthreads();

    // fused s1/s2: threads 0..63, one row each (uniform g_p loads broadcast)
    if (tid < 64) {
        int n = n0 + tid;
        if (n < NN) {
            float d1 = 0.f, d2 = 0.f;
            #pragma unroll 16
            for (int k = 0; k < 128; k += 2) {
                float2 xv = __half22float2(*(__half2*)&sX[tid * 136 + k]);
                d1 = fmaf(xv.x, g_p1[k], d1);
                d1 = fmaf(xv.y, g_p1[k + 1], d1);
                d2 = fmaf(xv.x, g_p2[k], d2);
                d2 = fmaf(xv.y, g_p2[k + 1], d2);
            }
            g_s1[n] = d1;
            g_s2[n] = d2;
        }
    }

    wmma::fragment<wmma::matrix_a, 16, 16, 16, half, wmma::row_major> af;
    wmma::fragment<wmma::matrix_b, 16, 16, 16, half, wmma::col_major> bf;
    wmma::fragment<wmma::accumulator, 16, 16, 16, float> acc[2];
    #pragma unroll
    for (int j = 0; j < 2; j++) wmma::fill_fragment(acc[j], 0.f);

    #pragma unroll
    for (int ks = 0; ks < 8; ks++) {
        wmma::load_matrix_sync(af, sX + rg * 16 * 136 + ks * 16, 136);
        #pragma unroll
        for (int j = 0; j < 2; j++) {
            wmma::load_matrix_sync(bf, sB + (cg * 32 + j * 16) * 136 + ks * 16, 136);
            wmma::mma_sync(acc[j], af, bf, acc[j]);
        }
    }
    __syncthreads();   // all sX reads (incl. s12) done before stage overwrite

    #pragma unroll
    for (int j = 0; j < 2; j++)
        wmma::store_matrix_sync(stage + rg * 16 * 64 + cg * 32 + j * 16, acc[j], 64,
                                wmma::mem_row_major);
    __syncthreads();

    for (int i = tid; i < 64 * 32; i += 256) {
        int r  = i >> 5;
        int c2 = i & 31;
        int n = n0 + r;
        if (n < NN) {
            __half2 h = __floats2half2_rn(stage[r * 64 + c2 * 2],
                                          stage[r * 64 + c2 * 2 + 1]);
            *(__half2*)&g_hv[(size_t)n * 64 + c2 * 2] = h;
        }
    }
}

// ---------------- scan phase 1: per-block exclusive scan (49 blocks) ---------
__global__ void __launch_bounds__(1024) k_scan1() {
    __shared__ int warpsum[32];
    int tid = threadIdx.x;
    int gid = blockIdx.x * 1024 + tid;
    int lane = tid & 31;
    int wid  = tid >> 5;

    int v = (gid < NN) ? g_cnt[gid] : 0;

    int x = v;
    #pragma unroll
    for (int o = 1; o < 32; o <<= 1) {
        int y = __shfl_up_sync(0xffffffffu, x, o);
        if (lane >= o) x += y;
    }
    if (lane == 31) warpsum[wid] = x;
    __syncthreads();

    if (wid == 0) {
        int w = warpsum[lane];
        int xw = w;
        #pragma unroll
        for (int o = 1; o < 32; o <<= 1) {
            int y = __shfl_up_sync(0xffffffffu, xw, o);
            if (lane >= o) xw += y;
        }
        warpsum[lane] = xw - w;
        if (lane == 31) g_bsum[blockIdx.x] = xw;
    }
    __syncthreads();

    int excl = x - v + warpsum[wid];
    if (gid < NN) g_off[gid] = excl;
}

// ---------------- scan phase 2+3: add block prefix, fill g_cur, zero g_cnt ---
__global__ void __launch_bounds__(1024) k_scan23() {
    __shared__ int spre;
    int b = blockIdx.x;
    if (threadIdx.x < 32) {
        int lane = threadIdx.x;
        int acc = 0;
        for (int j = lane; j < b; j += 32) acc += g_bsum[j];
        #pragma unroll
        for (int o = 16; o; o >>= 1) acc += __shfl_xor_sync(0xffffffffu, acc, o);
        if (lane == 0) spre = acc;
    }
    __syncthreads();
    int gid = b * 1024 + threadIdx.x;
    if (gid < NN) {
        int o = g_off[gid] + spre;
        g_off[gid] = o;
        g_cur[gid] = o;
        g_cnt[gid] = 0;               // restore invariant for next replay
    }
    if (b == 0 && threadIdx.x == 0) g_off[NN] = NE;   // counts sum to NE
}

// ---------------- fused logit + exp + scatter into CSR (4 edges/thread) ------
__global__ void k_scatter(const float* __restrict__ td, const int* __restrict__ src,
                          const int* __restrict__ dst, const float* __restrict__ omega) {
    int i = blockIdx.x * 256 + threadIdx.x;
    if (i * 4 >= NE) return;
    float4 t4 = ((const float4*)td)[i];
    int4   s4 = ((const int4*)src)[i];
    int4   d4 = ((const int4*)dst)[i];

    float tv[4] = {t4.x, t4.y, t4.z, t4.w};
    int   sv[4] = {s4.x, s4.y, s4.z, s4.w};
    int   dv[4] = {d4.x, d4.y, d4.z, d4.w};

    #pragma unroll
    for (int j = 0; j < 4; j++) {
        float t = tv[j];
        int s = sv[j], d = dv[j];
        float tt;
        if (t >= 0.f && t <= 1.f) {
            float u = t * (float)TABN;
            int i0 = (int)u;
            if (i0 >= TABN) i0 = TABN - 1;
            float f = u - (float)i0;
            float v0 = g_tab[i0], v1 = g_tab[i0 + 1];
            tt = v0 + f * (v1 - v0);
        } else {
            float acc = 0.f;
            for (int jj = 0; jj < THALF; jj++) {
                float sn, cs;
                sincosf(t * omega[jj], &sn, &cs);
                acc += sn * g_q[2 * jj] + cs * g_q[2 * jj + 1];
            }
            tt = acc * TSCALE;
        }
        float e = g_s1[s] + g_s2[d] + tt;
        e = (e > 0.f) ? e : 0.2f * e;       // LeakyReLU(0.2)
        float w = __expf(e);                // softmax numerator (logits are O(1))
        int pos = atomicAdd(&g_cur[d], 1);
        g_pair[pos] = make_float2(w, __int_as_float(s));
    }
}

// ---------------- warp-per-node single-pass softmax-aggregate ----------------
__global__ void k_agg(float* __restrict__ out) {
    int n = blockIdx.x * 8 + (threadIdx.x >> 5);
    int lane = threadIdx.x & 31;
    if (n >= NN) return;
    int start = g_off[n], end = g_off[n + 1];

    float wsum = 0.f, ax = 0.f, ay = 0.f;
    int k = start;
    for (; k + 4 <= end; k += 4) {
        float2 p0 = g_pair[k],     p1 = g_pair[k + 1];
        float2 p2 = g_pair[k + 2], p3 = g_pair[k + 3];
        int j0 = __float_as_int(p0.y), j1 = __float_as_int(p1.y);
        int j2 = __float_as_int(p2.y), j3 = __float_as_int(p3.y);
        __half2 h0 = ((const __half2*)(g_hv + (size_t)j0 * 64))[lane];
        __half2 h1 = ((const __half2*)(g_hv + (size_t)j1 * 64))[lane];
        __half2 h2 = ((const __half2*)(g_hv + (size_t)j2 * 64))[lane];
        __half2 h3 = ((const __half2*)(g_hv + (size_t)j3 * 64))[lane];
        float2 v0 = __half22float2(h0), v1 = __half22float2(h1);
        float2 v2 = __half22float2(h2), v3 = __half22float2(h3);
        wsum += (p0.x + p1.x) + (p2.x + p3.x);
        ax = fmaf(p0.x, v0.x, ax); ay = fmaf(p0.x, v0.y, ay);
        ax = fmaf(p1.x, v1.x, ax); ay = fmaf(p1.x, v1.y, ay);
        ax = fmaf(p2.x, v2.x, ax); ay = fmaf(p2.x, v2.y, ay);
        ax = fmaf(p3.x, v3.x, ax); ay = fmaf(p3.x, v3.y, ay);
    }
    for (; k < end; k++) {
        float2 p = g_pair[k];
        float2 v = __half22float2(
            ((const __half2*)(g_hv + (size_t)__float_as_int(p.y) * 64))[lane]);
        wsum += p.x;
        ax = fmaf(p.x, v.x, ax);
        ay = fmaf(p.x, v.y, ay);
    }
    float inv = (end > start) ? 1.f / wsum : 0.f;
    ((float2*)(out + (size_t)n * 64))[lane] = make_float2(ax * inv, ay * inv);
}

// ---------------- launcher: 3 branches, minimal critical path ----------------
extern "C" void kernel_launch(void* const* d_in, const int* in_sizes, int n_in,
                              void* d_out, int out_size) {
    const float* node_feats = (const float*)d_in[0];
    const float* time_diff  = (const float*)d_in[1];
    const int*   src        = (const int*)d_in[2];
    const int*   dst        = (const int*)d_in[3];
    const float* W          = (const float*)d_in[4];
    const float* Wv         = (const float*)d_in[5];
    const float* omega      = (const float*)d_in[6];
    const float* Wt         = (const float*)d_in[7];
    const float* a          = (const float*)d_in[8];
    float* out = (float*)d_out;

    static cudaStream_t sB = nullptr, sC = nullptr;
    static cudaEvent_t evFork = nullptr, evSetup = nullptr, evScan = nullptr, evHv = nullptr;
    if (!sB) {
        cudaStreamCreateWithFlags(&sB, cudaStreamNonBlocking);
        cudaStreamCreateWithFlags(&sC, cudaStreamNonBlocking);
        cudaEventCreateWithFlags(&evFork,  cudaEventDisableTiming);
        cudaEventCreateWithFlags(&evSetup, cudaEventDisableTiming);
        cudaEventCreateWithFlags(&evScan,  cudaEventDisableTiming);
        cudaEventCreateWithFlags(&evHv,    cudaEventDisableTiming);
    }

    // branch B (t=0): CSR build — needs only dst
    cudaEventRecord(evFork, 0);
    cudaStreamWaitEvent(sB, evFork, 0);
    k_count <<<CNT_BLOCKS, 256, 0, sB>>>(dst);
    k_scan1 <<<SCAN_BLOCKS, 1024, 0, sB>>>();
    k_scan23<<<SCAN_BLOCKS, 1024, 0, sB>>>();
    cudaEventRecord(evScan, sB);

    // main: weight prep (p1/p2, q, table)
    k_setup<<<19, 256>>>(W, Wt, a, omega);
    cudaEventRecord(evSetup, 0);

    // branch C: tensor-core hv + fused s1/s2 (X read once)
    cudaStreamWaitEvent(sC, evSetup, 0);
    k_hv<<<(NN + 63) / 64, 256, 0, sC>>>(node_feats, Wv);
    cudaEventRecord(evHv, sC);

    // main: join all, then scatter -> aggregate
    cudaStreamWaitEvent(0, evScan, 0);
    cudaStreamWaitEvent(0, evHv, 0);
    k_scatter<<<(NE / 4 + 255) / 256, 256>>>(time_diff, src, dst, omega);
    k_agg<<<(NN + 7) / 8, 256>>>(out);
}

// round 15
// speedup vs baseline: 1.5728x; 1.0056x over previous
#include <cuda_runtime.h>
#include <cuda_fp16.h>
#include <mma.h>
#include <math.h>

using namespace nvcuda;

#define NN 50000
#define NE 800000
#define IND 128
#define OUTD 64
#define THALF 64
#define TABN 4096
#define SCAN_BLOCKS 49           // ceil(50000 / 1024)
#define CNT_BLOCKS 391           // ceil(NE/8/256)

// sqrt(1/128)
#define TSCALE 0.08838834764831845f

// ---------------- scratch (static __device__, no allocations) ----------------
__device__ float  g_p1[IND];
__device__ float  g_p2[IND];
__device__ float  g_q[2 * THALF];
__device__ float  g_tab[TABN + 1];
__device__ float  g_s1[NN];
__device__ float  g_s2[NN];
__device__ __align__(32) __half g_hv[NN * OUTD];      // fp16 value rows
__device__ float2 g_pair[NE];                 // (w=exp(leaky(e)), bitcast(src))
__device__ int    g_cnt[NN];                  // zero-init at load; self-restoring
__device__ int    g_off[NN + 1];
__device__ int    g_cur[NN];
__device__ int    g_bsum[SCAN_BLOCKS];

// ---------------- p1/p2 only (1 block) — the sole dependency of k_hv ---------
__global__ void k_p12(const float* __restrict__ W, const float* __restrict__ a) {
    int t = threadIdx.x;    // 256 threads
    if (t < 128) {
        float s = 0.f;
        #pragma unroll 8
        for (int i = 0; i < 64; i++) s += W[i * 128 + t] * a[i];
        g_p1[t] = s;
    } else {
        int k = t - 128;
        float s = 0.f;
        #pragma unroll 8
        for (int i = 0; i < 64; i++) s += W[i * 128 + k] * a[64 + i];
        g_p2[k] = s;
    }
}

// ---------------- q + temporal table (17 blocks, smem-cached omega/qs) -------
__global__ void k_tabq(const float* __restrict__ Wt, const float* __restrict__ a,
                       const float* __restrict__ omega) {
    __shared__ float qs[128];
    __shared__ float om[THALF];
    int b = blockIdx.x;
    int t = threadIdx.x;

    if (t < 128) {
        float s = 0.f;
        #pragma unroll 8
        for (int i = 0; i < 64; i++) s += Wt[i * 128 + t] * a[128 + i];
        qs[t] = s;
        if (b == 0) g_q[t] = s;     // global copy for scatter's OOR fallback
    }
    if (t >= 128 && t < 128 + THALF) om[t - 128] = omega[t - 128];
    __syncthreads();

    int idx = b * 256 + t;          // 17*256 = 4352 >= TABN+1
    if (idx <= TABN) {
        float tt = (float)idx / (float)TABN;
        float s = 0.f;
        #pragma unroll 8
        for (int j = 0; j < THALF; j++) {
            float sn, cs;
            __sincosf(tt * om[j], &sn, &cs);
            s += sn * qs[2 * j] + cs * qs[2 * j + 1];
        }
        g_tab[idx] = s * TSCALE;
    }
}

// ---------------- degree histogram (8 edges per thread, 2x int4 load) --------
__global__ void k_count(const int* __restrict__ dst) {
    int i = blockIdx.x * 256 + threadIdx.x;      // NE/8 = 100000 threads
    if (i * 8 >= NE) return;
    int4 a4 = ((const int4*)dst)[i * 2];
    int4 b4 = ((const int4*)dst)[i * 2 + 1];
    atomicAdd(&g_cnt[a4.x], 1);
    atomicAdd(&g_cnt[a4.y], 1);
    atomicAdd(&g_cnt[a4.z], 1);
    atomicAdd(&g_cnt[a4.w], 1);
    atomicAdd(&g_cnt[b4.x], 1);
    atomicAdd(&g_cnt[b4.y], 1);
    atomicAdd(&g_cnt[b4.z], 1);
    atomicAdd(&g_cnt[b4.w], 1);
}

// ---------------- hv = X @ Wv^T via wmma + fused s1/s2 -----------------------
__global__ void __launch_bounds__(256) k_hv(const float* __restrict__ x,
                                            const float* __restrict__ Wv) {
    __shared__ __align__(32) half sX[64 * 136];    // 17408 B
    __shared__ __align__(32) half sB[64 * 136];    // 17408 B
    float* stage = (float*)sX;                     // aliased, sync-guarded

    int n0 = blockIdx.x * 64;
    int tid = threadIdx.x;
    int wid = tid >> 5;
    int rg = wid >> 1;          // row group 0..3
    int cg = wid & 1;           // col group 0..1

    // load + convert B: Wv[n][k] fp32 -> sB[n*136+k] fp16 (L2-resident source)
    for (int i = tid; i < 2048; i += 256) {
        int n  = i >> 5;
        int c4 = i & 31;
        float4 v = *(const float4*)(Wv + n * 128 + c4 * 4);
        *(__half2*)&sB[n * 136 + c4 * 4]     = __floats2half2_rn(v.x, v.y);
        *(__half2*)&sB[n * 136 + c4 * 4 + 2] = __floats2half2_rn(v.z, v.w);
    }

    // load X tile fp32 -> fp16
    for (int i = tid; i < 64 * 32; i += 256) {
        int r  = i >> 5;
        int c4 = i & 31;
        int n = n0 + r;
        float4 v = (n < NN)
            ? *(const float4*)(x + (size_t)n * 128 + c4 * 4)
            : make_float4(0.f, 0.f, 0.f, 0.f);
        *(__half2*)&sX[r * 136 + c4 * 4]     = __floats2half2_rn(v.x, v.y);
        *(__half2*)&sX[r * 136 + c4 * 4 + 2] = __floats2half2_rn(v.z, v.w);
    }
    __syncthreads();

    // fused s1/s2: threads 0..63, one row each (uniform g_p loads broadcast)
    if (tid < 64) {
        int n = n0 + tid;
        if (n < NN) {
            float d1 = 0.f, d2 = 0.f;
            #pragma unroll 16
            for (int k = 0; k < 128; k += 2) {
                float2 xv = __half22float2(*(__half2*)&sX[tid * 136 + k]);
                d1 = fmaf(xv.x, g_p1[k], d1);
                d1 = fmaf(xv.y, g_p1[k + 1], d1);
                d2 = fmaf(xv.x, g_p2[k], d2);
                d2 = fmaf(xv.y, g_p2[k + 1], d2);
            }
            g_s1[n] = d1;
            g_s2[n] = d2;
        }
    }

    wmma::fragment<wmma::matrix_a, 16, 16, 16, half, wmma::row_major> af;
    wmma::fragment<wmma::matrix_b, 16, 16, 16, half, wmma::col_major> bf;
    wmma::fragment<wmma::accumulator, 16, 16, 16, float> acc[2];
    #pragma unroll
    for (int j = 0; j < 2; j++) wmma::fill_fragment(acc[j], 0.f);

    #pragma unroll
    for (int ks = 0; ks < 8; ks++) {
        wmma::load_matrix_sync(af, sX + rg * 16 * 136 + ks * 16, 136);
        #pragma unroll
        for (int j = 0; j < 2; j++) {
            wmma::load_matrix_sync(bf, sB + (cg * 32 + j * 16) * 136 + ks * 16, 136);
            wmma::mma_sync(acc[j], af, bf, acc[j]);
        }
    }
    __syncthreads();   // all sX reads (incl. s12) done before stage overwrite

    #pragma unroll
    for (int j = 0; j < 2; j++)
        wmma::store_matrix_sync(stage + rg * 16 * 64 + cg * 32 + j * 16, acc[j], 64,
                                wmma::mem_row_major);
    __syncthreads();

    for (int i = tid; i < 64 * 32; i += 256) {
        int r  = i >> 5;
        int c2 = i & 31;
        int n = n0 + r;
        if (n < NN) {
            __half2 h = __floats2half2_rn(stage[r * 64 + c2 * 2],
                                          stage[r * 64 + c2 * 2 + 1]);
            *(__half2*)&g_hv[(size_t)n * 64 + c2 * 2] = h;
        }
    }
}

// ---------------- scan phase 1: per-block exclusive scan (49 blocks) ---------
__global__ void __launch_bounds__(1024) k_scan1() {
    __shared__ int warpsum[32];
    int tid = threadIdx.x;
    int gid = blockIdx.x * 1024 + tid;
    int lane = tid & 31;
    int wid  = tid >> 5;

    int v = (gid < NN) ? g_cnt[gid] : 0;

    int x = v;
    #pragma unroll
    for (int o = 1; o < 32; o <<= 1) {
        int y = __shfl_up_sync(0xffffffffu, x, o);
        if (lane >= o) x += y;
    }
    if (lane == 31) warpsum[wid] = x;
    __syncthreads();

    if (wid == 0) {
        int w = warpsum[lane];
        int xw = w;
        #pragma unroll
        for (int o = 1; o < 32; o <<= 1) {
            int y = __shfl_up_sync(0xffffffffu, xw, o);
            if (lane >= o) xw += y;
        }
        warpsum[lane] = xw - w;
        if (lane == 31) g_bsum[blockIdx.x] = xw;
    }
    __syncthreads();

    int excl = x - v + warpsum[wid];
    if (gid < NN) g_off[gid] = excl;
}

// ---------------- scan phase 2+3: add block prefix, fill g_cur, zero g_cnt ---
__global__ void __launch_bounds__(1024) k_scan23() {
    __shared__ int spre;
    int b = blockIdx.x;
    if (threadIdx.x < 32) {
        int lane = threadIdx.x;
        int acc = 0;
        for (int j = lane; j < b; j += 32) acc += g_bsum[j];
        #pragma unroll
        for (int o = 16; o; o >>= 1) acc += __shfl_xor_sync(0xffffffffu, acc, o);
        if (lane == 0) spre = acc;
    }
    __syncthreads();
    int gid = b * 1024 + threadIdx.x;
    if (gid < NN) {
        int o = g_off[gid] + spre;
        g_off[gid] = o;
        g_cur[gid] = o;
        g_cnt[gid] = 0;               // restore invariant for next replay
    }
    if (b == 0 && threadIdx.x == 0) g_off[NN] = NE;   // counts sum to NE
}

// ---------------- fused logit + exp + scatter into CSR (4 edges/thread) ------
__global__ void k_scatter(const float* __restrict__ td, const int* __restrict__ src,
                          const int* __restrict__ dst, const float* __restrict__ omega) {
    int i = blockIdx.x * 256 + threadIdx.x;
    if (i * 4 >= NE) return;
    float4 t4 = ((const float4*)td)[i];
    int4   s4 = ((const int4*)src)[i];
    int4   d4 = ((const int4*)dst)[i];

    float tv[4] = {t4.x, t4.y, t4.z, t4.w};
    int   sv[4] = {s4.x, s4.y, s4.z, s4.w};
    int   dv[4] = {d4.x, d4.y, d4.z, d4.w};

    #pragma unroll
    for (int j = 0; j < 4; j++) {
        float t = tv[j];
        int s = sv[j], d = dv[j];
        float tt;
        if (t >= 0.f && t <= 1.f) {
            float u = t * (float)TABN;
            int i0 = (int)u;
            if (i0 >= TABN) i0 = TABN - 1;
            float f = u - (float)i0;
            float v0 = g_tab[i0], v1 = g_tab[i0 + 1];
            tt = v0 + f * (v1 - v0);
        } else {
            float acc = 0.f;
            for (int jj = 0; jj < THALF; jj++) {
                float sn, cs;
                sincosf(t * omega[jj], &sn, &cs);
                acc += sn * g_q[2 * jj] + cs * g_q[2 * jj + 1];
            }
            tt = acc * TSCALE;
        }
        float e = g_s1[s] + g_s2[d] + tt;
        e = (e > 0.f) ? e : 0.2f * e;       // LeakyReLU(0.2)
        float w = __expf(e);                // softmax numerator (logits are O(1))
        int pos = atomicAdd(&g_cur[d], 1);
        g_pair[pos] = make_float2(w, __int_as_float(s));
    }
}

// ---------------- warp-per-node single-pass softmax-aggregate ----------------
__global__ void k_agg(float* __restrict__ out) {
    int n = blockIdx.x * 8 + (threadIdx.x >> 5);
    int lane = threadIdx.x & 31;
    if (n >= NN) return;
    int start = g_off[n], end = g_off[n + 1];

    float wsum = 0.f, ax = 0.f, ay = 0.f;
    int k = start;
    for (; k + 4 <= end; k += 4) {
        float2 p0 = g_pair[k],     p1 = g_pair[k + 1];
        float2 p2 = g_pair[k + 2], p3 = g_pair[k + 3];
        int j0 = __float_as_int(p0.y), j1 = __float_as_int(p1.y);
        int j2 = __float_as_int(p2.y), j3 = __float_as_int(p3.y);
        __half2 h0 = ((const __half2*)(g_hv + (size_t)j0 * 64))[lane];
        __half2 h1 = ((const __half2*)(g_hv + (size_t)j1 * 64))[lane];
        __half2 h2 = ((const __half2*)(g_hv + (size_t)j2 * 64))[lane];
        __half2 h3 = ((const __half2*)(g_hv + (size_t)j3 * 64))[lane];
        float2 v0 = __half22float2(h0), v1 = __half22float2(h1);
        float2 v2 = __half22float2(h2), v3 = __half22float2(h3);
        wsum += (p0.x + p1.x) + (p2.x + p3.x);
        ax = fmaf(p0.x, v0.x, ax); ay = fmaf(p0.x, v0.y, ay);
        ax = fmaf(p1.x, v1.x, ax); ay = fmaf(p1.x, v1.y, ay);
        ax = fmaf(p2.x, v2.x, ax); ay = fmaf(p2.x, v2.y, ay);
        ax = fmaf(p3.x, v3.x, ax); ay = fmaf(p3.x, v3.y, ay);
    }
    for (; k < end; k++) {
        float2 p = g_pair[k];
        float2 v = __half22float2(
            ((const __half2*)(g_hv + (size_t)__float_as_int(p.y) * 64))[lane]);
        wsum += p.x;
        ax = fmaf(p.x, v.x, ax);
        ay = fmaf(p.x, v.y, ay);
    }
    float inv = (end > start) ? 1.f / wsum : 0.f;
    ((float2*)(out + (size_t)n * 64))[lane] = make_float2(ax * inv, ay * inv);
}

// ---------------- launcher: 4 branches, minimal critical path ----------------
extern "C" void kernel_launch(void* const* d_in, const int* in_sizes, int n_in,
                              void* d_out, int out_size) {
    const float* node_feats = (const float*)d_in[0];
    const float* time_diff  = (const float*)d_in[1];
    const int*   src        = (const int*)d_in[2];
    const int*   dst        = (const int*)d_in[3];
    const float* W          = (const float*)d_in[4];
    const float* Wv         = (const float*)d_in[5];
    const float* omega      = (const float*)d_in[6];
    const float* Wt         = (const float*)d_in[7];
    const float* a          = (const float*)d_in[8];
    float* out = (float*)d_out;

    static cudaStream_t sB = nullptr, sD = nullptr;
    static cudaEvent_t evFork = nullptr, evScan = nullptr, evTab = nullptr;
    if (!sB) {
        cudaStreamCreateWithFlags(&sB, cudaStreamNonBlocking);
        cudaStreamCreateWithFlags(&sD, cudaStreamNonBlocking);
        cudaEventCreateWithFlags(&evFork, cudaEventDisableTiming);
        cudaEventCreateWithFlags(&evScan, cudaEventDisableTiming);
        cudaEventCreateWithFlags(&evTab,  cudaEventDisableTiming);
    }

    cudaEventRecord(evFork, 0);

    // branch B (t=0): CSR build — needs only dst
    cudaStreamWaitEvent(sB, evFork, 0);
    k_count <<<CNT_BLOCKS, 256, 0, sB>>>(dst);
    k_scan1 <<<SCAN_BLOCKS, 1024, 0, sB>>>();
    k_scan23<<<SCAN_BLOCKS, 1024, 0, sB>>>();
    cudaEventRecord(evScan, sB);

    // branch D (t=0): q + temporal table — needed only by scatter
    cudaStreamWaitEvent(sD, evFork, 0);
    k_tabq<<<17, 256, 0, sD>>>(Wt, a, omega);
    cudaEventRecord(evTab, sD);

    // main chain: p1/p2 -> hv(+s12) -> join -> scatter -> agg
    k_p12<<<1, 256>>>(W, a);
    k_hv<<<(NN + 63) / 64, 256>>>(node_feats, Wv);
    cudaStreamWaitEvent(0, evScan, 0);
    cudaStreamWaitEvent(0, evTab, 0);
    k_scatter<<<(NE / 4 + 255) / 256, 256>>>(time_diff, src, dst, omega);
    k_agg<<<(NN + 7) / 8, 256>>>(out);
}